// round 15
// baseline (speedup 1.0000x reference)
#include <cuda_runtime.h>
#include <cuda_fp16.h>
#include <cstdint>
#include <cstring>

#define NB 4
#define NS 2048
#define NE 1024
#define NH 16
#define ND 64

// ======================= scratch (allocation-free) =========================
__device__ __half g_qh[(size_t)NB * NH * NS * ND];
__device__ __half g_kh[(size_t)NB * NH * NS * ND];
__device__ __half g_vh[(size_t)NB * NH * NS * ND];
__device__ __half g_xh[(size_t)NB * NS * NE];
__device__ __half g_ah[(size_t)NB * NS * NE];
__device__ __half g_wqkv[(size_t)3 * NE * NE];  // wq | wk | wv rows
__device__ __half g_woh[(size_t)NE * NE];

// ======================= warp-level MMA helpers ============================
__device__ __forceinline__ uint32_t smem_u32(const void* p) {
    uint32_t a;
    asm("{ .reg .u64 t; cvta.to.shared.u64 t, %1; cvt.u32.u64 %0, t; }"
        : "=r"(a) : "l"(p));
    return a;
}
__device__ __forceinline__ uint32_t h2_u32(__half2 h) {
    uint32_t u;
    memcpy(&u, &h, 4);
    return u;
}
__device__ __forceinline__ void ldm_x4(uint32_t addr, uint32_t* r) {
    asm volatile("ldmatrix.sync.aligned.m8n8.x4.shared.b16 {%0,%1,%2,%3}, [%4];"
                 : "=r"(r[0]), "=r"(r[1]), "=r"(r[2]), "=r"(r[3]) : "r"(addr));
}
__device__ __forceinline__ void ldm_x4_t(uint32_t addr, uint32_t* r) {
    asm volatile("ldmatrix.sync.aligned.m8n8.x4.trans.shared.b16 {%0,%1,%2,%3}, [%4];"
                 : "=r"(r[0]), "=r"(r[1]), "=r"(r[2]), "=r"(r[3]) : "r"(addr));
}
__device__ __forceinline__ void mma_f16(float* d, const uint32_t* a,
                                        const uint32_t* b) {
    asm volatile(
        "mma.sync.aligned.m16n8k16.row.col.f32.f16.f16.f32 "
        "{%0,%1,%2,%3}, {%4,%5,%6,%7}, {%8,%9}, {%0,%1,%2,%3};"
        : "+f"(d[0]), "+f"(d[1]), "+f"(d[2]), "+f"(d[3])
        : "r"(a[0]), "r"(a[1]), "r"(a[2]), "r"(a[3]), "r"(b[0]), "r"(b[1]));
}
#define CP_ASYNC16(dst, src)                                                   \
    asm volatile("cp.async.ca.shared.global [%0], [%1], 16;"                   \
                 :: "r"(dst), "l"(src) : "memory")
#define CP_COMMIT() asm volatile("cp.async.commit_group;" ::: "memory")
#define CP_WAIT1()  asm volatile("cp.async.wait_group 1;" ::: "memory")
#define CP_WAIT0()  asm volatile("cp.async.wait_group 0;" ::: "memory")

// ======================= fused conversion kernel ===========================
#define NX4 (NB * NS * NE / 4)
#define NW4 (NE * NE / 4)

__global__ void __launch_bounds__(256)
cvt_all(const float* __restrict__ x, const float* __restrict__ wq,
        const float* __restrict__ wk, const float* __restrict__ wv,
        const float* __restrict__ wo, __half* __restrict__ xh,
        __half* __restrict__ wqkv, __half* __restrict__ woh) {
    int i = blockIdx.x * 256 + threadIdx.x;
    const int total = NX4 + 4 * NW4;
    if (i >= total) return;
    const float* src;
    __half* dst;
    int j;
    if (i < NX4) {
        src = x; dst = xh; j = i;
    } else {
        int r = i - NX4;
        int t = r / NW4;
        j = r - t * NW4;
        src = (t == 0) ? wq : (t == 1) ? wk : (t == 2) ? wv : wo;
        dst = (t == 3) ? woh : wqkv + (size_t)t * NE * NE;
    }
    float4 v = reinterpret_cast<const float4*>(src)[j];
    __half2 p0 = __floats2half2_rn(v.x, v.y);
    __half2 p1 = __floats2half2_rn(v.z, v.w);
    reinterpret_cast<__half2*>(dst)[2 * j]     = p0;
    reinterpret_cast<__half2*>(dst)[2 * j + 1] = p1;
}

// ======================= fp16 1-pass GEMM via mma.sync =====================
// CTA 128x128, 4 warps (2m x 2n), warp tile 64x64.
// K-chunk 64 (4 k16 steps), 3-stage cp.async pipeline, 144B smem rows.
// SCATTER=1: fused QKV -> half outputs [B,H,S,D]; Q pre-scaled by 0.125.
// SCATTER=0: float row-major [M,1024].
#define GT_ROW_B 144                        // 128B data + 16B pad
#define GT_TILE_B (128 * GT_ROW_B)          // 18432 B
#define GT_STAGE_B (2 * GT_TILE_B)          // 36864 B (A + B)
#define GT_TOTAL (3 * GT_STAGE_B)           // 110592 B
#define GT_NCHUNK (NE / 64)                 // 16

template <int SCATTER>
__global__ void __launch_bounds__(128, 2)
gemm_mma(const __half* __restrict__ Ah, const __half* __restrict__ Bh,
         void* __restrict__ C0, void* __restrict__ C1, void* __restrict__ C2) {
    extern __shared__ __align__(128) char smem[];
    const uint32_t sb = smem_u32(smem);
    const int tid = threadIdx.x;
    const int wid = tid >> 5, lane = tid & 31;
    const int wm = wid & 1, wn = wid >> 1;
    const size_t m0 = (size_t)blockIdx.y * 128;
    const size_t n0 = (size_t)blockIdx.x * 128;

    auto issue_chunk = [&](int c, int buf) {
        const int kofs = c * 64;
        const uint32_t base = sb + buf * GT_STAGE_B;
#pragma unroll
        for (int it = 0; it < 16; it++) {
            const int t = it >> 3;                  // 0=A, 1=B
            const int s = tid + (it & 7) * 128;     // 0..1023
            const int r = s >> 3;                   // 0..127
            const int g = s & 7;                    // 16B group in row
            const size_t row = (t == 0 ? m0 : n0) + r;
            const __half* gsrc = (t == 0 ? Ah : Bh) + row * NE + kofs + g * 8;
            const uint32_t dst = base + t * GT_TILE_B + r * GT_ROW_B + g * 16;
            CP_ASYNC16(dst, gsrc);
        }
        CP_COMMIT();
    };

    float acc[4][8][4];
#pragma unroll
    for (int mi = 0; mi < 4; mi++)
#pragma unroll
        for (int nj = 0; nj < 8; nj++)
#pragma unroll
            for (int e = 0; e < 4; e++) acc[mi][nj][e] = 0.f;

    const int a_row = wm * 64 + (lane & 15);
    const int a_kb  = (lane >> 4) * 16;
    const int b_row = wn * 64 + (lane >> 4) * 8 + (lane & 7);
    const int b_kb  = ((lane >> 3) & 1) * 16;

    issue_chunk(0, 0);
    issue_chunk(1, 1);
    for (int c = 0; c < GT_NCHUNK; c++) {
        const int buf = c % 3;
        if (c < GT_NCHUNK - 1) CP_WAIT1(); else CP_WAIT0();
        __syncthreads();
        if (c + 2 < GT_NCHUNK) issue_chunk(c + 2, (c + 2) % 3);

        const uint32_t ahb = sb + buf * GT_STAGE_B;
        const uint32_t bhb = ahb + GT_TILE_B;

#pragma unroll
        for (int kk = 0; kk < 4; kk++) {
            const int kbyte = kk * 32;
            uint32_t afh[4][4], bfh[4][4];
#pragma unroll
            for (int mi = 0; mi < 4; mi++)
                ldm_x4(ahb + (a_row + mi * 16) * GT_ROW_B + kbyte + a_kb,
                       afh[mi]);
#pragma unroll
            for (int j = 0; j < 4; j++)
                ldm_x4(bhb + (b_row + j * 16) * GT_ROW_B + kbyte + b_kb,
                       bfh[j]);
#pragma unroll
            for (int mi = 0; mi < 4; mi++)
#pragma unroll
                for (int j = 0; j < 4; j++) {
                    mma_f16(acc[mi][2 * j],     afh[mi], bfh[j]);
                    mma_f16(acc[mi][2 * j + 1], afh[mi], bfh[j] + 2);
                }
        }
        __syncthreads();
    }

    // ---- epilogue ----
    const int row_in = lane >> 2;
    const int col2 = 2 * (lane & 3);
    __half* hbase = nullptr;
    float qscale = 1.f;
    size_t hh = 0;
    if (SCATTER) {
        const size_t nglob = n0 + wn * 64;
        const int tsel = (int)(nglob >> 10);
        hbase = (__half*)(tsel == 0 ? C0 : (tsel == 1 ? C1 : C2));
        qscale = (tsel == 0) ? 0.125f : 1.0f;
        hh = (nglob & 1023) >> 6;
    }
#pragma unroll
    for (int mi = 0; mi < 4; mi++) {
#pragma unroll
        for (int h8 = 0; h8 < 2; h8++) {
            const size_t m = m0 + wm * 64 + mi * 16 + row_in + h8 * 8;
            if (SCATTER == 0) {
                float* dst = (float*)C0 + m * NE + n0 + wn * 64;
#pragma unroll
                for (int nj = 0; nj < 8; nj++) {
                    float2 v = h8 ? make_float2(acc[mi][nj][2], acc[mi][nj][3])
                                  : make_float2(acc[mi][nj][0], acc[mi][nj][1]);
                    *reinterpret_cast<float2*>(dst + nj * 8 + col2) = v;
                }
            } else {
                const size_t bbi = m / NS, ss = m % NS;
                __half* dst = hbase + ((bbi * NH + hh) * NS + ss) * ND;
#pragma unroll
                for (int nj = 0; nj < 8; nj++) {
                    __half2 v = h8 ? __floats2half2_rn(acc[mi][nj][2] * qscale,
                                                       acc[mi][nj][3] * qscale)
                                   : __floats2half2_rn(acc[mi][nj][0] * qscale,
                                                       acc[mi][nj][1] * qscale);
                    *reinterpret_cast<__half2*>(dst + nj * 8 + col2) = v;
                }
            }
        }
    }
}

// ======================= fp16 tensor-core flash attention ==================
// CTA: 128 q-rows; kv-outer tiles of 128 (two inner 64-col softmax passes).
// 4 warps, each 32 q-rows. Q fragments hoisted; K/V double-buffered cp.async.
#define ASH 144                        // smem row stride in bytes (72 halves)
#define AQ_OFF 0                       // Q: 128 * 144 = 18432 B
#define AKV_OFF 18432                  // 2 stages of (K 18432 + V 18432)
#define AKV_STAGE 36864
#define AAM_OFF (18432 + 2 * 36864)    // 92160: 2 x 128 ints
#define ATTN_SMEM (92160 + 1024 + 512)

__global__ void __launch_bounds__(128, 2)
attn_mma(const __half* __restrict__ Qg, const __half* __restrict__ Kg,
         const __half* __restrict__ Vg, const int* __restrict__ amask,
         __half* __restrict__ Oh) {
    extern __shared__ __align__(128) char smem[];
    const uint32_t sb = smem_u32(smem);
    int* s_am = reinterpret_cast<int*>(smem + AAM_OFF);

    const int tid = threadIdx.x;
    const int wid = tid >> 5, lane = tid & 31;
    const int qt = blockIdx.x;
    const int q0 = qt * 128;
    const int bh = blockIdx.y;
    const int b = bh / NH;
    const int h = bh % NH;

    const __half* qg = Qg + (size_t)bh * NS * ND;
    const __half* kg = Kg + (size_t)bh * NS * ND;
    const __half* vg = Vg + (size_t)bh * NS * ND;

    auto issue_kv = [&](int kt_, int bf) {
        const int k0_ = kt_ * 128;
        const uint32_t base = sb + AKV_OFF + bf * AKV_STAGE;
#pragma unroll
        for (int it = 0; it < 16; it++) {
            const int hs = it >> 3;                 // 0=K, 1=V
            const int s = tid + (it & 7) * 128;     // 0..1023
            const int r = s >> 3, g = s & 7;
            const __half* src = (hs ? vg : kg) + (size_t)(k0_ + r) * ND + g * 8;
            CP_ASYNC16(base + hs * 18432 + r * ASH + g * 16, src);
        }
        CP_COMMIT();
    };

    issue_kv(0, 0);

    // Q tile -> smem (128 rows x 128 B)
#pragma unroll
    for (int it = 0; it < 8; it++) {
        int s = tid + it * 128;
        int r = s >> 3, g = s & 7;
        uint4 v = *reinterpret_cast<const uint4*>(qg + (size_t)(q0 + r) * ND + g * 8);
        *reinterpret_cast<uint4*>(smem + AQ_OFF + r * ASH + g * 16) = v;
    }
    s_am[tid] = amask[b * NS + tid];
    __syncthreads();

    // hoisted Q fragments (constant across kv loop)
    uint32_t qf[4][2][4];
    const uint32_t qb = sb + AQ_OFF;
#pragma unroll
    for (int t = 0; t < 4; t++)
#pragma unroll
        for (int mi = 0; mi < 2; mi++)
            ldm_x4(qb + (wid * 32 + mi * 16 + (lane & 15)) * ASH +
                       (lane >> 4) * 16 + t * 32, qf[t][mi]);

    float acco[2][8][4];
    float m_[2][2], l_[2][2];
#pragma unroll
    for (int mi = 0; mi < 2; mi++) {
        m_[mi][0] = m_[mi][1] = -1e30f;
        l_[mi][0] = l_[mi][1] = 0.f;
#pragma unroll
        for (int nj = 0; nj < 8; nj++)
#pragma unroll
            for (int e = 0; e < 4; e++) acco[mi][nj][e] = 0.f;
    }

    const int qrow0 = q0 + wid * 32;
    const int ntiles = qt + 1;

    for (int kt = 0; kt < ntiles; kt++) {
        const int buf = kt & 1;
        const bool pre = (kt + 1 < ntiles);
        int amreg = pre ? amask[b * NS + (kt + 1) * 128 + tid] : 0;

        __syncthreads();                 // prior tile's readers done with buf^1
        if (pre) {
            issue_kv(kt + 1, buf ^ 1);
            s_am[(buf ^ 1) * 128 + tid] = amreg;
            CP_WAIT1();
        } else {
            CP_WAIT0();
        }
        __syncthreads();                 // tile kt (K/V + amask) visible

        const uint32_t kb0 = sb + AKV_OFF + buf * AKV_STAGE;

#pragma unroll
        for (int h2 = 0; h2 < 2; h2++) {
            const int k0 = kt * 128 + h2 * 64;
            if (k0 > qrow0 + 31) continue;   // whole warp masked: exact no-op

            const uint32_t kb = kb0 + h2 * 64 * ASH;
            const uint32_t vb = kb0 + 18432 + h2 * 64 * ASH;

            // pad-mask bits for this thread's 16 columns
            uint32_t pm = 0;
#pragma unroll
            for (int jj = 0; jj < 16; jj++) {
                int c = 8 * (jj >> 1) + 2 * (lane & 3) + (jj & 1);
                pm |= (uint32_t)(s_am[buf * 128 + h2 * 64 + c] != 0) << jj;
            }

            // ---- S = Q K^T (Q pre-scaled) ----
            float sacc[2][8][4];
#pragma unroll
            for (int mi = 0; mi < 2; mi++)
#pragma unroll
                for (int nj = 0; nj < 8; nj++)
#pragma unroll
                    for (int e = 0; e < 4; e++) sacc[mi][nj][e] = 0.f;

#pragma unroll
            for (int t = 0; t < 4; t++) {
                uint32_t bf[4][4];
#pragma unroll
                for (int j = 0; j < 4; j++)
                    ldm_x4(kb + (j * 16 + (lane >> 4) * 8 + (lane & 7)) * ASH +
                               ((lane >> 3) & 1) * 16 + t * 32, bf[j]);
#pragma unroll
                for (int mi = 0; mi < 2; mi++)
#pragma unroll
                    for (int j = 0; j < 4; j++) {
                        mma_f16(sacc[mi][2 * j],     qf[t][mi], bf[j]);
                        mma_f16(sacc[mi][2 * j + 1], qf[t][mi], bf[j] + 2);
                    }
            }

            // ---- mask ----
#pragma unroll
            for (int mi = 0; mi < 2; mi++)
#pragma unroll
                for (int nj = 0; nj < 8; nj++)
#pragma unroll
                    for (int e = 0; e < 4; e++) {
                        int qi = qrow0 + mi * 16 + (lane >> 2) + (e >> 1) * 8;
                        int kj = k0 + 8 * nj + 2 * (lane & 3) + (e & 1);
                        bool bad = (kj > qi) || !((pm >> (2 * nj + (e & 1))) & 1);
                        if (bad) sacc[mi][nj][e] = -1e30f;
                    }

            // ---- online softmax; P -> fp16 A-fragments in registers ----
            uint32_t u0[2][8], u1[2][8];
#pragma unroll
            for (int mi = 0; mi < 2; mi++) {
                float mx0 = -1e30f, mx1 = -1e30f;
#pragma unroll
                for (int nj = 0; nj < 8; nj++) {
                    mx0 = fmaxf(mx0, fmaxf(sacc[mi][nj][0], sacc[mi][nj][1]));
                    mx1 = fmaxf(mx1, fmaxf(sacc[mi][nj][2], sacc[mi][nj][3]));
                }
                mx0 = fmaxf(mx0, __shfl_xor_sync(0xffffffffu, mx0, 1));
                mx0 = fmaxf(mx0, __shfl_xor_sync(0xffffffffu, mx0, 2));
                mx1 = fmaxf(mx1, __shfl_xor_sync(0xffffffffu, mx1, 1));
                mx1 = fmaxf(mx1, __shfl_xor_sync(0xffffffffu, mx1, 2));

                float mn0 = fmaxf(m_[mi][0], mx0);
                float mn1 = fmaxf(m_[mi][1], mx1);
                float f0 = __expf(m_[mi][0] - mn0);
                float f1 = __expf(m_[mi][1] - mn1);
                m_[mi][0] = mn0; m_[mi][1] = mn1;

                float s0 = 0.f, s1 = 0.f;
#pragma unroll
                for (int nj = 0; nj < 8; nj++) {
                    float p00 = __expf(sacc[mi][nj][0] - mn0);
                    float p01 = __expf(sacc[mi][nj][1] - mn0);
                    float p10 = __expf(sacc[mi][nj][2] - mn1);
                    float p11 = __expf(sacc[mi][nj][3] - mn1);
                    s0 += p00 + p01; s1 += p10 + p11;
                    u0[mi][nj] = h2_u32(__floats2half2_rn(p00, p01));
                    u1[mi][nj] = h2_u32(__floats2half2_rn(p10, p11));
                }
                s0 += __shfl_xor_sync(0xffffffffu, s0, 1);
                s0 += __shfl_xor_sync(0xffffffffu, s0, 2);
                s1 += __shfl_xor_sync(0xffffffffu, s1, 1);
                s1 += __shfl_xor_sync(0xffffffffu, s1, 2);
                l_[mi][0] = l_[mi][0] * f0 + s0;
                l_[mi][1] = l_[mi][1] * f1 + s1;
#pragma unroll
                for (int nj = 0; nj < 8; nj++) {
                    acco[mi][nj][0] *= f0; acco[mi][nj][1] *= f0;
                    acco[mi][nj][2] *= f1; acco[mi][nj][3] *= f1;
                }
            }

            // ---- O += P V ----
#pragma unroll
            for (int t = 0; t < 4; t++) {
                uint32_t vf[4][4];
#pragma unroll
                for (int jn = 0; jn < 4; jn++)
                    ldm_x4_t(vb + (t * 16 + ((lane >> 3) & 1) * 8 + (lane & 7)) * ASH +
                                 jn * 32 + (lane >> 4) * 16, vf[jn]);
#pragma unroll
                for (int mi = 0; mi < 2; mi++) {
                    uint32_t a[4] = {u0[mi][2 * t], u1[mi][2 * t],
                                     u0[mi][2 * t + 1], u1[mi][2 * t + 1]};
#pragma unroll
                    for (int nj = 0; nj < 8; nj++)
                        mma_f16(acco[mi][nj], a, vf[nj >> 1] + (nj & 1) * 2);
                }
            }
        }
    }

    // ---- epilogue: O /= l, fp16 into [B,S,E] ----
#pragma unroll
    for (int mi = 0; mi < 2; mi++) {
        float inv0 = 1.f / l_[mi][0];
        float inv1 = 1.f / l_[mi][1];
        int r0 = q0 + wid * 32 + mi * 16 + (lane >> 2);
        int col = h * ND + 2 * (lane & 3);
#pragma unroll
        for (int nj = 0; nj < 8; nj++) {
            __half2 o0 = __floats2half2_rn(acco[mi][nj][0] * inv0,
                                           acco[mi][nj][1] * inv0);
            __half2 o1 = __floats2half2_rn(acco[mi][nj][2] * inv1,
                                           acco[mi][nj][3] * inv1);
            *reinterpret_cast<__half2*>(Oh + (size_t)(b * NS + r0) * NE + col + 8 * nj) = o0;
            *reinterpret_cast<__half2*>(Oh + (size_t)(b * NS + r0 + 8) * NE + col + 8 * nj) = o1;
        }
    }
}

// ======================= launcher ==========================================
extern "C" void kernel_launch(void* const* d_in, const int* in_sizes, int n_in,
                              void* d_out, int out_size) {
    (void)in_sizes; (void)n_in; (void)out_size;
    const float* x  = (const float*)d_in[0];
    const int*   am = (const int*)d_in[1];
    const float* wq = (const float*)d_in[2];
    const float* wk = (const float*)d_in[3];
    const float* wv = (const float*)d_in[4];
    const float* wo = (const float*)d_in[5];
    float* out = (float*)d_out;

    __half *qh, *kh, *vh, *xh, *ah, *wqkv, *woh;
    cudaGetSymbolAddress((void**)&qh, g_qh);
    cudaGetSymbolAddress((void**)&kh, g_kh);
    cudaGetSymbolAddress((void**)&vh, g_vh);
    cudaGetSymbolAddress((void**)&xh, g_xh);
    cudaGetSymbolAddress((void**)&ah, g_ah);
    cudaGetSymbolAddress((void**)&wqkv, g_wqkv);
    cudaGetSymbolAddress((void**)&woh, g_woh);

    const int total4 = NX4 + 4 * NW4;
    cvt_all<<<(total4 + 255) / 256, 256>>>(x, wq, wk, wv, wo, xh, wqkv, woh);

    cudaFuncSetAttribute(gemm_mma<0>, cudaFuncAttributeMaxDynamicSharedMemorySize, GT_TOTAL);
    cudaFuncSetAttribute(gemm_mma<1>, cudaFuncAttributeMaxDynamicSharedMemorySize, GT_TOTAL);
    cudaFuncSetAttribute(attn_mma, cudaFuncAttributeMaxDynamicSharedMemorySize, ATTN_SMEM);

    gemm_mma<1><<<dim3(3 * NE / 128, (NB * NS) / 128), 128, GT_TOTAL>>>(
        xh, wqkv, qh, kh, vh);

    attn_mma<<<dim3(NS / 128, NB * NH), 128, ATTN_SMEM>>>(qh, kh, vh, am, ah);

    gemm_mma<0><<<dim3(NE / 128, (NB * NS) / 128), 128, GT_TOTAL>>>(
        ah, woh, out, nullptr, nullptr);
}